// round 15
// baseline (speedup 1.0000x reference)
#include <cuda_runtime.h>
#include <cuda_fp16.h>
#include <mma.h>
using namespace nvcuda;

#define NN   100000
#define EE   1600000
#define ET   (EE + NN)        // 1,700,000 incl self-loops
#define FIN  128
#define H1   8
#define C1   64
#define C2   40
#define NEG  0.2f
#define NCHUNK 98             // ceil(NN/1024)

// ---------------- scratch (device globals; allocation-free) ----------------
__device__ int     g_cnt [NN];
__device__ int     g_row [NN + 1];
__device__ int     g_cur [NN];
__device__ int     g_srcs[ET];
__device__ int     g_csum[NCHUNK];
__device__ int     g_coff[NCHUNK];
__device__ __half2 g_w1h [FIN * C1 / 2];   // W1 pre-converted to fp16 (L1-resident in gemm1)
__device__ __half2 g_h1h [NN * 32];        // h1 fp16, 32 half2 per node
__device__ float   g_as1 [NN * H1];
__device__ float   g_ad1 [NN * H1];
__device__ float   g_x2  [NN * C1];        // layer-2 input (post attention+lrelu)
__device__ __half  g_h2h [NN * C2];        // h2 fp16 (80B rows, 16B aligned)
__device__ float   g_as2 [NN];
__device__ float   g_ad2 [NN];
__device__ float   g_agg2[NN * C2];
__device__ float   g_den2[NN];
__device__ float   g_va  [C1];
__device__ float   g_vd  [C1];

__device__ __forceinline__ float lrelu(float x) { return x > 0.f ? x : NEG * x; }

// ================= zero counters + prep (W1->half, va/vd) =================
__global__ __launch_bounds__(256) void zero_prep_kernel(const float* __restrict__ W1,
                                                        const float* __restrict__ W2,
                                                        const float* __restrict__ asw,
                                                        const float* __restrict__ adw) {
    int i = blockIdx.x * 256 + threadIdx.x;
    if (i < NN) g_cnt[i] = 0;
    if (i < FIN * C1 / 2) {
        float2 v = ((const float2*)W1)[i];
        g_w1h[i] = __floats2half2_rn(v.x, v.y);
    }
    if (i < C1) {
        float s = 0.f, d = 0.f;
#pragma unroll
        for (int j = 0; j < C2; j++) { float w = W2[i * C2 + j]; s += w * asw[j]; d += w * adw[j]; }
        g_va[i] = s;
        g_vd[i] = d;
    }
}

// ================= CSR build =================
__global__ __launch_bounds__(256) void hist_kernel(const int* __restrict__ ei) {
    int e = blockIdx.x * 256 + threadIdx.x;
    if (e >= ET) return;
    int dst = (e < EE) ? ei[EE + e] : (e - EE);
    atomicAdd(&g_cnt[dst], 1);
}

__global__ __launch_bounds__(256) void scan_a_kernel() {
    __shared__ int sred[256];
    const int c = blockIdx.x, tid = threadIdx.x;
    int base = c * 1024 + tid * 4, s = 0;
#pragma unroll
    for (int i = 0; i < 4; i++) { int idx = base + i; if (idx < NN) s += g_cnt[idx]; }
    sred[tid] = s;
    __syncthreads();
    for (int o = 128; o; o >>= 1) {
        if (tid < o) sred[tid] += sred[tid + o];
        __syncthreads();
    }
    if (tid == 0) g_csum[c] = sred[0];
}

__global__ __launch_bounds__(128) void scan_b_kernel() {
    __shared__ int ws[4], wofs[4];
    const int t = threadIdx.x, lane = t & 31, warp = t >> 5;
    int v = (t < NCHUNK) ? g_csum[t] : 0;
    int incl = v;
#pragma unroll
    for (int o = 1; o < 32; o <<= 1) {
        int n = __shfl_up_sync(0xffffffffu, incl, o);
        if (lane >= o) incl += n;
    }
    if (lane == 31) ws[warp] = incl;
    __syncthreads();
    if (t == 0) { int a = 0; for (int w = 0; w < 4; w++) { wofs[w] = a; a += ws[w]; } }
    __syncthreads();
    if (t < NCHUNK) g_coff[t] = incl - v + wofs[warp];
}

__global__ __launch_bounds__(256) void scan_c_kernel() {
    __shared__ int ws[8], wofs[8];
    const int c = blockIdx.x, tid = threadIdx.x, lane = tid & 31, warp = tid >> 5;
    int base = c * 1024 + tid * 4;
    int v[4], s = 0;
#pragma unroll
    for (int i = 0; i < 4; i++) {
        int idx = base + i;
        v[i] = (idx < NN) ? g_cnt[idx] : 0;
        s += v[i];
    }
    int incl = s;
#pragma unroll
    for (int o = 1; o < 32; o <<= 1) {
        int n = __shfl_up_sync(0xffffffffu, incl, o);
        if (lane >= o) incl += n;
    }
    if (lane == 31) ws[warp] = incl;
    __syncthreads();
    if (tid == 0) { int a = 0; for (int w = 0; w < 8; w++) { wofs[w] = a; a += ws[w]; } }
    __syncthreads();
    int p = incl - s + wofs[warp] + g_coff[c];
#pragma unroll
    for (int i = 0; i < 4; i++) {
        int idx = base + i;
        if (idx < NN) {
            g_row[idx] = p;
            g_cur[idx] = p;
            p += v[i];
            if (idx == NN - 1) g_row[NN] = p;
        }
    }
}

__global__ __launch_bounds__(256) void scatter_kernel(const int* __restrict__ ei) {
    int e = blockIdx.x * 256 + threadIdx.x;
    if (e >= ET) return;
    int src, dst;
    if (e < EE) { src = ei[e]; dst = ei[EE + e]; }
    else        { src = dst = e - EE; }
    int pos = atomicAdd(&g_cur[dst], 1);
    g_srcs[pos] = src;
}

// ================= layer1 GEMM via fp16 wmma, high-occupancy =================
// 128 threads (4 warps), 64 nodes/block. Only x staged in smem; B-fragments
// load directly from g_w1h (16KB, L1-resident). warp w: rows [16w,16w+16).
#define XH_LD 136        // 64 rows x 136 half (pad 8)  = 17,408 B
#define CB_LD 68         // 64 rows x 68 f32 (epilogue) = 17,408 B (aliases xh)
__global__ __launch_bounds__(128, 7) void gemm1_kernel(const float* __restrict__ x,
                                                       const float* __restrict__ asw,
                                                       const float* __restrict__ adw) {
    __shared__ __align__(16) unsigned char sraw[64 * XH_LD * 2];   // 17,408 B
    __half* xh = (__half*)sraw;                          // [64][136]
    float*  cb = (float*)sraw;                           // [64][68] (aliases xh post-mainloop)

    const int tid = threadIdx.x, warp = tid >> 5;
    const int node0 = blockIdx.x * 64;
    const float4* x4 = (const float4*)x;
    const __half* wp = (const __half*)g_w1h;             // [128][64] row-major

    // stage x tile: 64 rows x 32 float4 = 2048 over 128 threads (with fp16 convert)
#pragma unroll
    for (int i = 0; i < 16; i++) {
        int idx = tid + i * 128;
        int node = idx >> 5, kq = idx & 31;
        int gn = node0 + node; if (gn >= NN) gn = NN - 1;
        float4 v = x4[(size_t)gn * 32 + kq];
        __half2* dp = (__half2*)&xh[node * XH_LD + kq * 4];
        dp[0] = __floats2half2_rn(v.x, v.y);
        dp[1] = __floats2half2_rn(v.z, v.w);
    }
    __syncthreads();

    wmma::fragment<wmma::accumulator, 16, 16, 16, float> c[4];
#pragma unroll
    for (int n = 0; n < 4; n++) wmma::fill_fragment(c[n], 0.f);

#pragma unroll
    for (int ks = 0; ks < 8; ks++) {
        wmma::fragment<wmma::matrix_a, 16, 16, 16, __half, wmma::row_major> a;
        wmma::load_matrix_sync(a, xh + (warp * 16) * XH_LD + ks * 16, XH_LD);
#pragma unroll
        for (int n = 0; n < 4; n++) {
            wmma::fragment<wmma::matrix_b, 16, 16, 16, __half, wmma::row_major> b;
            wmma::load_matrix_sync(b, wp + (ks * 16) * C1 + n * 16, C1);   // global, L1-hot
            wmma::mma_sync(c[n], a, b, c[n]);
        }
    }
    __syncthreads();            // xh dead -> reuse as cb
#pragma unroll
    for (int n = 0; n < 4; n++)
        wmma::store_matrix_sync(cb + (warp * 16) * CB_LD + n * 16, c[n], CB_LD, wmma::mem_row_major);
    __syncthreads();

    // epilogue: 2 threads/node; h selects channels [32h, 32h+32) = heads 4h..4h+3
    const int node = tid >> 1, h = tid & 1;
    const int gn = node0 + node;
    const float* row = cb + node * CB_LD + h * 32;
    if (gn < NN) {
#pragma unroll
        for (int hh = 0; hh < 4; hh++) {
            int head = h * 4 + hh;
            float ps = 0.f, pd = 0.f;
#pragma unroll
            for (int j = 0; j < 8; j++) {
                float cv = row[hh * 8 + j];
                ps += cv * asw[head * 8 + j];
                pd += cv * adw[head * 8 + j];
            }
            g_as1[gn * H1 + head] = ps;
            g_ad1[gn * H1 + head] = pd;
        }
#pragma unroll
        for (int q = 0; q < 16; q++)
            g_h1h[gn * 32 + h * 16 + q] = __floats2half2_rn(row[2 * q], row[2 * q + 1]);
    }
}

// ====== layer1 gather (fp16 h1) + fused layer2-input transform ======
// warp per dst node; lane handles channel pair (2*lane, 2*lane+1), head = lane>>2.
// Two-phase 8-edge sub-batches: phase A = 8 independent as1-loads+exp (MLP 8),
// phase B = 8 independent h1h-loads+FMA.
__global__ __launch_bounds__(256) void gather1_kernel(const float* __restrict__ b1) {
    const int gw = (blockIdx.x * 256 + threadIdx.x) >> 5;
    const int lane = threadIdx.x & 31;
    if (gw >= NN) return;
    const int beg = g_row[gw], end = g_row[gw + 1];

    const float myad = (lane < H1) ? g_ad1[gw * H1 + lane] : 0.f;
    float accx = 0.f, accy = 0.f, den = 0.f;

    for (int base = beg; base < end; base += 32) {
        int nv = end - base; if (nv > 32) nv = 32;
        int s = g_srcs[base + (lane < nv ? lane : 0)];
        for (int jb = 0; jb < nv; jb += 8) {
            float w8[8];
            int   s8[8];
#pragma unroll
            for (int u = 0; u < 8; u++) {
                int j = jb + u;
                s8[u] = __shfl_sync(0xffffffffu, s, j & 31);
                float myw = 0.f;
                if (lane < H1 && j < nv)
                    myw = __expf(lrelu(g_as1[s8[u] * H1 + lane] + myad));
                w8[u] = myw;            // 0 when inactive -> den stays correct
            }
#pragma unroll
            for (int u = 0; u < 8; u++) {
                int j = jb + u;
                den += w8[u];
                if (j < nv) {           // warp-uniform branch
                    float w = __shfl_sync(0xffffffffu, w8[u], lane >> 2);
                    float2 f = __half22float2(g_h1h[s8[u] * 32 + lane]);
                    accx += f.x * w;
                    accy += f.y * w;
                }
            }
        }
    }
    // fused: x2 = lrelu(agg/den + b1)
    float d = __shfl_sync(0xffffffffu, den, lane >> 2);
    float2 bb = *(const float2*)&b1[2 * lane];
    float2 o;
    o.x = lrelu(__fdividef(accx, d) + bb.x);
    o.y = lrelu(__fdividef(accy, d) + bb.y);
    *(float2*)&g_x2[gw * C1 + 2 * lane] = o;
}

// ====== layer2 GEMM: h2 = x2@W2 (fp16, smem-staged vector stores); logits via va/vd ======
// 256 threads, 128 nodes/block, 4 nodes/thread
__global__ __launch_bounds__(256) void gemm2_kernel(const float* __restrict__ W2) {
    __shared__ float sW2[C1 * C2];       // 10,240B; reused as sh2[128][40] half after mainloop
    __shared__ float sx2[128 * 65];      // 33.3KB (stride 65 -> conflict-free col reads)
    __shared__ float sva[C1], svd[C1];
    const int tid = threadIdx.x;
    const int node0 = blockIdx.x * 128;

    for (int i = tid; i < C1 * C2; i += 256) sW2[i] = W2[i];
    if (tid < C1) { sva[tid] = g_va[tid]; svd[tid] = g_vd[tid]; }
    for (int i = tid; i < 128 * C1 / 4; i += 256) {
        int node = i >> 4, cq = i & 15;
        int gn = node0 + node;
        float4 v = make_float4(0.f, 0.f, 0.f, 0.f);
        if (gn < NN) v = *(const float4*)&g_x2[gn * C1 + cq * 4];
        float* dstp = &sx2[node * 65 + cq * 4];   // scalar stores (row stride not 16B aligned)
        dstp[0] = v.x; dstp[1] = v.y; dstp[2] = v.z; dstp[3] = v.w;
    }
    __syncthreads();

    const int lane = tid & 31, grp = tid >> 5, ob = grp * 5;
    float acc[4][5] = {};
#pragma unroll 4
    for (int k = 0; k < C1; k++) {
        float w0 = sW2[k * C2 + ob + 0], w1 = sW2[k * C2 + ob + 1],
              w2 = sW2[k * C2 + ob + 2], w3 = sW2[k * C2 + ob + 3],
              w4 = sW2[k * C2 + ob + 4];
#pragma unroll
        for (int i = 0; i < 4; i++) {
            float xv = sx2[(lane + 32 * i) * 65 + k];
            acc[i][0] += xv * w0; acc[i][1] += xv * w1; acc[i][2] += xv * w2;
            acc[i][3] += xv * w3; acc[i][4] += xv * w4;
        }
    }

    // logits: 2 threads per node, 32 channels each (reads sx2/sva/svd only)
    {
        const int node = tid >> 1, h = tid & 1;
        const int gn = node0 + node;
        float s = 0.f, d = 0.f;
        const float* xr = &sx2[node * 65 + h * 32];
        const float* va = &sva[h * 32];
        const float* vd = &svd[h * 32];
#pragma unroll 8
        for (int k = 0; k < 32; k++) { float xv = xr[k]; s += xv * va[k]; d += xv * vd[k]; }
        s += __shfl_xor_sync(0xffffffffu, s, 1);
        d += __shfl_xor_sync(0xffffffffu, d, 1);
        if (h == 0 && gn < NN) { g_as2[gn] = s; g_ad2[gn] = d; }
    }

    // h2 fp16: stage into sW2-region smem, then aligned 16B vector stores
    __syncthreads();                         // all mainloop reads of sW2 done
    __half* sh2 = (__half*)sW2;              // [128][40] = 10,240B exactly
#pragma unroll
    for (int i = 0; i < 4; i++) {
        __half* rp = &sh2[(lane + 32 * i) * 40 + ob];
#pragma unroll
        for (int j = 0; j < 5; j++) rp[j] = __float2half(acc[i][j]);
    }
    __syncthreads();
    // 128 nodes x 5 uint4 (80B) = 640 vector stores
    for (int i = tid; i < 640; i += 256) {
        int node = i / 5, q = i - node * 5;
        int gn = node0 + node;
        if (gn < NN)
            *(uint4*)&g_h2h[gn * C2 + q * 8] = *(const uint4*)&sh2[node * 40 + q * 8];
    }
}

// ================= layer2 gather (fp16 h2): warp per dst node =================
// lane < 10 handles 4 channels [4*lane, 4*lane+4) via one 8B load
__global__ __launch_bounds__(256) void gather2_kernel() {
    const int gw = (blockIdx.x * 256 + threadIdx.x) >> 5;
    const int lane = threadIdx.x & 31;
    if (gw >= NN) return;
    const int beg = g_row[gw], end = g_row[gw + 1];

    const float myad = g_ad2[gw];
    float a0 = 0.f, a1 = 0.f, a2 = 0.f, a3 = 0.f, den = 0.f;

    for (int base = beg; base < end; base += 32) {
        int nv = end - base; if (nv > 32) nv = 32;
        int s = g_srcs[base + (lane < nv ? lane : 0)];
        float wl = __expf(lrelu(g_as2[s] + myad));   // per-lane precomputed weight
        for (int j = 0; j < nv; j++) {
            int src = __shfl_sync(0xffffffffu, s, j);
            float w = __shfl_sync(0xffffffffu, wl, j);
            if (lane < 10) {
                uint2 p = *(const uint2*)&g_h2h[src * C2 + lane * 4];
                float2 f0 = __half22float2(*(__half2*)&p.x);
                float2 f1 = __half22float2(*(__half2*)&p.y);
                a0 += f0.x * w; a1 += f0.y * w; a2 += f1.x * w; a3 += f1.y * w;
            }
            den += w;
        }
    }
    if (lane < 10) {
        float4 o; o.x = a0; o.y = a1; o.z = a2; o.w = a3;
        *(float4*)&g_agg2[gw * C2 + lane * 4] = o;
    }
    if (lane == 0) g_den2[gw] = den;
}

// ================= final: log_softmax =================
__global__ __launch_bounds__(256) void final_kernel(const float* __restrict__ b2,
                                                    float* __restrict__ out) {
    const int warp = threadIdx.x >> 5, lane = threadIdx.x & 31;
    const int n = blockIdx.x * 8 + warp;
    const float inv = __fdividef(1.f, g_den2[n]);
    const float* agg = &g_agg2[(size_t)n * C2];
    float v0 = agg[lane] * inv + b2[lane];
    float v1 = (lane < 8) ? agg[32 + lane] * inv + b2[32 + lane] : -1e30f;
    float m = fmaxf(v0, v1);
#pragma unroll
    for (int o = 16; o; o >>= 1) m = fmaxf(m, __shfl_xor_sync(0xffffffffu, m, o));
    float s = __expf(v0 - m) + ((lane < 8) ? __expf(v1 - m) : 0.f);
#pragma unroll
    for (int o = 16; o; o >>= 1) s += __shfl_xor_sync(0xffffffffu, s, o);
    float lse = m + __logf(s);
    out[n * C2 + lane] = v0 - lse;
    if (lane < 8) out[n * C2 + 32 + lane] = v1 - lse;
}

// ================= launch =================
extern "C" void kernel_launch(void* const* d_in, const int* in_sizes, int n_in,
                              void* d_out, int out_size) {
    const float* x   = (const float*)d_in[0];
    const int*   ei  = (const int*)  d_in[1];
    const float* W1  = (const float*)d_in[2];
    const float* as1 = (const float*)d_in[3];
    const float* ad1 = (const float*)d_in[4];
    const float* b1  = (const float*)d_in[5];
    const float* W2  = (const float*)d_in[6];
    const float* as2 = (const float*)d_in[7];
    const float* ad2 = (const float*)d_in[8];
    const float* b2  = (const float*)d_in[9];
    float* out = (float*)d_out;

    const int EB = (ET + 255) / 256;

    zero_prep_kernel<<<(NN + 255) / 256, 256>>>(W1, W2, as2, ad2);
    hist_kernel     <<<EB, 256>>>(ei);
    scan_a_kernel   <<<NCHUNK, 256>>>();
    gemm1_kernel    <<<(NN + 63) / 64, 128>>>(x, as1, ad1);      // 4th launch -> profiled
    scan_b_kernel   <<<1, 128>>>();
    scan_c_kernel   <<<NCHUNK, 256>>>();
    scatter_kernel  <<<EB, 256>>>(ei);
    gather1_kernel  <<<(NN * 32 + 255) / 256, 256>>>(b1);
    gemm2_kernel    <<<(NN + 127) / 128, 256>>>(W2);
    gather2_kernel  <<<(NN * 32 + 255) / 256, 256>>>();
    final_kernel    <<<NN / 8, 256>>>(b2, out);
}

// round 16
// speedup vs baseline: 1.3468x; 1.3468x over previous
#include <cuda_runtime.h>
#include <cuda_fp16.h>
#include <mma.h>
using namespace nvcuda;

#define NN   100000
#define EE   1600000
#define ET   (EE + NN)        // 1,700,000 incl self-loops
#define FIN  128
#define H1   8
#define C1   64
#define C2   40
#define NEG  0.2f
#define NCHUNK 98             // ceil(NN/1024)

// ---------------- scratch (device globals; allocation-free) ----------------
__device__ int     g_cnt [NN];
__device__ int     g_row [NN + 1];
__device__ int     g_cur [NN];
__device__ int     g_srcs[ET];
__device__ int     g_csum[NCHUNK];
__device__ int     g_coff[NCHUNK];
__device__ __half2 g_h1h [NN * 32];   // h1 fp16, 32 half2 per node
__device__ float   g_as1 [NN * H1];
__device__ float   g_ad1 [NN * H1];
__device__ float   g_x2  [NN * C1];   // layer-2 input (post attention+lrelu)
__device__ float   g_h2  [NN * C2];
__device__ float   g_as2 [NN];
__device__ float   g_ad2 [NN];
__device__ float   g_va  [C1];
__device__ float   g_vd  [C1];

__device__ __forceinline__ float lrelu(float x) { return x > 0.f ? x : NEG * x; }

// ================= zero counters + va/vd precompute =================
__global__ __launch_bounds__(256) void zero_prep_kernel(const float* __restrict__ W2,
                                                        const float* __restrict__ asw,
                                                        const float* __restrict__ adw) {
    int i = blockIdx.x * 256 + threadIdx.x;
    if (i < NN) g_cnt[i] = 0;
    if (i < C1) {
        float s = 0.f, d = 0.f;
#pragma unroll
        for (int j = 0; j < C2; j++) { float w = W2[i * C2 + j]; s += w * asw[j]; d += w * adw[j]; }
        g_va[i] = s;
        g_vd[i] = d;
    }
}

// ================= CSR build =================
__global__ __launch_bounds__(256) void hist_kernel(const int* __restrict__ ei) {
    int e = blockIdx.x * 256 + threadIdx.x;
    if (e >= ET) return;
    int dst = (e < EE) ? ei[EE + e] : (e - EE);
    atomicAdd(&g_cnt[dst], 1);
}

__global__ __launch_bounds__(256) void scan_a_kernel() {
    __shared__ int sred[256];
    const int c = blockIdx.x, tid = threadIdx.x;
    int base = c * 1024 + tid * 4, s = 0;
#pragma unroll
    for (int i = 0; i < 4; i++) { int idx = base + i; if (idx < NN) s += g_cnt[idx]; }
    sred[tid] = s;
    __syncthreads();
    for (int o = 128; o; o >>= 1) {
        if (tid < o) sred[tid] += sred[tid + o];
        __syncthreads();
    }
    if (tid == 0) g_csum[c] = sred[0];
}

__global__ __launch_bounds__(128) void scan_b_kernel() {
    __shared__ int ws[4], wofs[4];
    const int t = threadIdx.x, lane = t & 31, warp = t >> 5;
    int v = (t < NCHUNK) ? g_csum[t] : 0;
    int incl = v;
#pragma unroll
    for (int o = 1; o < 32; o <<= 1) {
        int n = __shfl_up_sync(0xffffffffu, incl, o);
        if (lane >= o) incl += n;
    }
    if (lane == 31) ws[warp] = incl;
    __syncthreads();
    if (t == 0) { int a = 0; for (int w = 0; w < 4; w++) { wofs[w] = a; a += ws[w]; } }
    __syncthreads();
    if (t < NCHUNK) g_coff[t] = incl - v + wofs[warp];
}

__global__ __launch_bounds__(256) void scan_c_kernel() {
    __shared__ int ws[8], wofs[8];
    const int c = blockIdx.x, tid = threadIdx.x, lane = tid & 31, warp = tid >> 5;
    int base = c * 1024 + tid * 4;
    int v[4], s = 0;
#pragma unroll
    for (int i = 0; i < 4; i++) {
        int idx = base + i;
        v[i] = (idx < NN) ? g_cnt[idx] : 0;
        s += v[i];
    }
    int incl = s;
#pragma unroll
    for (int o = 1; o < 32; o <<= 1) {
        int n = __shfl_up_sync(0xffffffffu, incl, o);
        if (lane >= o) incl += n;
    }
    if (lane == 31) ws[warp] = incl;
    __syncthreads();
    if (tid == 0) { int a = 0; for (int w = 0; w < 8; w++) { wofs[w] = a; a += ws[w]; } }
    __syncthreads();
    int p = incl - s + wofs[warp] + g_coff[c];
#pragma unroll
    for (int i = 0; i < 4; i++) {
        int idx = base + i;
        if (idx < NN) {
            g_row[idx] = p;
            g_cur[idx] = p;
            p += v[i];
            if (idx == NN - 1) g_row[NN] = p;
        }
    }
}

__global__ __launch_bounds__(256) void scatter_kernel(const int* __restrict__ ei) {
    int e = blockIdx.x * 256 + threadIdx.x;
    if (e >= ET) return;
    int src, dst;
    if (e < EE) { src = ei[e]; dst = ei[EE + e]; }
    else        { src = dst = e - EE; }
    int pos = atomicAdd(&g_cur[dst], 1);
    g_srcs[pos] = src;
}

// ================= layer1 GEMM via fp16 wmma, occupancy-first (R13-validated) ==========
// 128 threads (4 warps), 64 nodes/block. x-tile + FULL W1 staged once; no
// mid-loop syncs. warp w computes rows [16w,16w+16) x all 64 channels, K=128.
#define XH_LD 136        // 64 rows x 136 half (pad 8)  = 17,408 B
#define WH_LD 72         // 128 rows x 72 half (pad 8)  = 18,432 B
#define CB_LD 68         // 64 rows x 68 f32 (epilogue) = 17,408 B (aliases xh)
__global__ __launch_bounds__(128, 6) void gemm1_kernel(const float* __restrict__ x,
                                                       const float* __restrict__ W1,
                                                       const float* __restrict__ asw,
                                                       const float* __restrict__ adw) {
    __shared__ __align__(16) unsigned char sraw[64 * XH_LD * 2 + 128 * WH_LD * 2]; // 35,840 B
    __half* xh = (__half*)sraw;                          // [64][136]
    __half* wh = (__half*)(sraw + 64 * XH_LD * 2);       // [128][72]
    float*  cb = (float*)sraw;                           // [64][68] (aliases xh post-mainloop)

    const int tid = threadIdx.x, warp = tid >> 5;
    const int node0 = blockIdx.x * 64;
    const float4* x4 = (const float4*)x;
    const float4* W4 = (const float4*)W1;

    // stage x tile: 64 rows x 32 float4 = 2048 over 128 threads
#pragma unroll
    for (int i = 0; i < 16; i++) {
        int idx = tid + i * 128;
        int node = idx >> 5, kq = idx & 31;
        int gn = node0 + node; if (gn >= NN) gn = NN - 1;
        float4 v = x4[(size_t)gn * 32 + kq];
        __half2* dp = (__half2*)&xh[node * XH_LD + kq * 4];
        dp[0] = __floats2half2_rn(v.x, v.y);
        dp[1] = __floats2half2_rn(v.z, v.w);
    }
    // stage full W1: 128 rows x 16 float4 = 2048 over 128 threads
#pragma unroll
    for (int i = 0; i < 16; i++) {
        int idx = tid + i * 128;
        int k = idx >> 4, cq = idx & 15;
        float4 w = W4[(size_t)k * 16 + cq];
        __half2* dp = (__half2*)&wh[k * WH_LD + cq * 4];
        dp[0] = __floats2half2_rn(w.x, w.y);
        dp[1] = __floats2half2_rn(w.z, w.w);
    }
    __syncthreads();

    wmma::fragment<wmma::accumulator, 16, 16, 16, float> c[4];
#pragma unroll
    for (int n = 0; n < 4; n++) wmma::fill_fragment(c[n], 0.f);

#pragma unroll
    for (int ks = 0; ks < 8; ks++) {
        wmma::fragment<wmma::matrix_a, 16, 16, 16, __half, wmma::row_major> a;
        wmma::load_matrix_sync(a, xh + (warp * 16) * XH_LD + ks * 16, XH_LD);
#pragma unroll
        for (int n = 0; n < 4; n++) {
            wmma::fragment<wmma::matrix_b, 16, 16, 16, __half, wmma::row_major> b;
            wmma::load_matrix_sync(b, wh + (ks * 16) * WH_LD + n * 16, WH_LD);
            wmma::mma_sync(c[n], a, b, c[n]);
        }
    }
    __syncthreads();            // xh dead -> reuse as cb
#pragma unroll
    for (int n = 0; n < 4; n++)
        wmma::store_matrix_sync(cb + (warp * 16) * CB_LD + n * 16, c[n], CB_LD, wmma::mem_row_major);
    __syncthreads();

    // epilogue: 2 threads/node; h selects channels [32h, 32h+32) = heads 4h..4h+3
    const int node = tid >> 1, h = tid & 1;
    const int gn = node0 + node;
    const float* row = cb + node * CB_LD + h * 32;
    if (gn < NN) {
#pragma unroll
        for (int hh = 0; hh < 4; hh++) {
            int head = h * 4 + hh;
            float ps = 0.f, pd = 0.f;
#pragma unroll
            for (int j = 0; j < 8; j++) {
                float cv = row[hh * 8 + j];
                ps += cv * asw[head * 8 + j];
                pd += cv * adw[head * 8 + j];
            }
            g_as1[gn * H1 + head] = ps;
            g_ad1[gn * H1 + head] = pd;
        }
#pragma unroll
        for (int q = 0; q < 16; q++)
            g_h1h[gn * 32 + h * 16 + q] = __floats2half2_rn(row[2 * q], row[2 * q + 1]);
    }
}

// ====== layer1 gather (fp16 h1) + fused layer2-input transform (R13-validated) ======
// warp per dst node; lane handles channel pair (2*lane, 2*lane+1), head = lane>>2
__global__ __launch_bounds__(256) void gather1_kernel(const float* __restrict__ b1) {
    const int gw = (blockIdx.x * 256 + threadIdx.x) >> 5;
    const int lane = threadIdx.x & 31;
    if (gw >= NN) return;
    const int beg = g_row[gw], end = g_row[gw + 1];

    const float myad = (lane < H1) ? g_ad1[gw * H1 + lane] : 0.f;
    float accx = 0.f, accy = 0.f, den = 0.f;

    for (int base = beg; base < end; base += 32) {
        int nv = end - base; if (nv > 32) nv = 32;
        int s = g_srcs[base + (lane < nv ? lane : 0)];
        for (int j = 0; j < nv; j++) {
            int src = __shfl_sync(0xffffffffu, s, j);
            float myw = 0.f;
            if (lane < H1)
                myw = __expf(lrelu(g_as1[src * H1 + lane] + myad));
            den += myw;                                        // lanes 0-7: per-head den
            float w = __shfl_sync(0xffffffffu, myw, lane >> 2);
            float2 f = __half22float2(g_h1h[src * 32 + lane]);
            accx += f.x * w;
            accy += f.y * w;
        }
    }
    // fused: x2 = lrelu(agg/den + b1)
    float d = __shfl_sync(0xffffffffu, den, lane >> 2);
    float2 bb = *(const float2*)&b1[2 * lane];
    float2 o;
    o.x = lrelu(__fdividef(accx, d) + bb.x);
    o.y = lrelu(__fdividef(accy, d) + bb.y);
    *(float2*)&g_x2[gw * C1 + 2 * lane] = o;
}

// ================= layer2 GEMM: h2 = x2@W2; logits via va/vd (R13-validated) ==========
// 256 threads, 128 nodes/block, 4 nodes/thread
__global__ __launch_bounds__(256) void gemm2_kernel(const float* __restrict__ W2) {
    __shared__ float sW2[C1 * C2];       // 10KB
    __shared__ float sx2[128 * 65];      // 33.3KB (stride 65 -> conflict-free col reads)
    __shared__ float sva[C1], svd[C1];
    const int tid = threadIdx.x;
    const int node0 = blockIdx.x * 128;

    for (int i = tid; i < C1 * C2; i += 256) sW2[i] = W2[i];
    if (tid < C1) { sva[tid] = g_va[tid]; svd[tid] = g_vd[tid]; }
    for (int i = tid; i < 128 * C1 / 4; i += 256) {
        int node = i >> 4, cq = i & 15;
        int gn = node0 + node;
        float4 v = make_float4(0.f, 0.f, 0.f, 0.f);
        if (gn < NN) v = *(const float4*)&g_x2[gn * C1 + cq * 4];
        float* dstp = &sx2[node * 65 + cq * 4];   // scalar stores (row stride not 16B aligned)
        dstp[0] = v.x; dstp[1] = v.y; dstp[2] = v.z; dstp[3] = v.w;
    }
    __syncthreads();

    const int lane = tid & 31, grp = tid >> 5, ob = grp * 5;
    float acc[4][5] = {};
#pragma unroll 4
    for (int k = 0; k < C1; k++) {
        float w0 = sW2[k * C2 + ob + 0], w1 = sW2[k * C2 + ob + 1],
              w2 = sW2[k * C2 + ob + 2], w3 = sW2[k * C2 + ob + 3],
              w4 = sW2[k * C2 + ob + 4];
#pragma unroll
        for (int i = 0; i < 4; i++) {
            float xv = sx2[(lane + 32 * i) * 65 + k];
            acc[i][0] += xv * w0; acc[i][1] += xv * w1; acc[i][2] += xv * w2;
            acc[i][3] += xv * w3; acc[i][4] += xv * w4;
        }
    }
#pragma unroll
    for (int i = 0; i < 4; i++) {
        int gn = node0 + lane + 32 * i;
        if (gn < NN) {
#pragma unroll
            for (int j = 0; j < 5; j++) g_h2[gn * C2 + ob + j] = acc[i][j];
        }
    }

    // logits: 2 threads per node, 32 channels each
    const int node = tid >> 1, h = tid & 1;
    const int gn = node0 + node;
    float s = 0.f, d = 0.f;
    const float* xr = &sx2[node * 65 + h * 32];
    const float* va = &sva[h * 32];
    const float* vd = &svd[h * 32];
#pragma unroll 8
    for (int k = 0; k < 32; k++) { float xv = xr[k]; s += xv * va[k]; d += xv * vd[k]; }
    s += __shfl_xor_sync(0xffffffffu, s, 1);
    d += __shfl_xor_sync(0xffffffffu, d, 1);
    if (h == 0 && gn < NN) { g_as2[gn] = s; g_ad2[gn] = d; }
}

// ====== layer2 gather + FUSED log_softmax: warp per dst node, atomic-free ======
__global__ __launch_bounds__(256) void gather2_kernel(const float* __restrict__ b2,
                                                      float* __restrict__ out) {
    const int gw = (blockIdx.x * 256 + threadIdx.x) >> 5;
    const int lane = threadIdx.x & 31;
    if (gw >= NN) return;
    const int beg = g_row[gw], end = g_row[gw + 1];

    const float myad = g_ad2[gw];
    float acc0 = 0.f, acc1 = 0.f, den = 0.f;

    for (int base = beg; base < end; base += 32) {
        int nv = end - base; if (nv > 32) nv = 32;
        int s = g_srcs[base + (lane < nv ? lane : 0)];
        float wl = __expf(lrelu(g_as2[s] + myad));   // per-lane precomputed weight
        for (int j = 0; j < nv; j++) {
            int src = __shfl_sync(0xffffffffu, s, j);
            float w = __shfl_sync(0xffffffffu, wl, j);
            acc0 += g_h2[src * C2 + lane] * w;
            if (lane < 8) acc1 += g_h2[src * C2 + 32 + lane] * w;
            den += w;                                // identical across lanes
        }
    }

    // fused log_softmax over the 40 in-register channels
    const float inv = __fdividef(1.f, den);
    float v0 = acc0 * inv + b2[lane];
    float v1 = (lane < 8) ? acc1 * inv + b2[32 + lane] : -1e30f;
    float m = fmaxf(v0, v1);
#pragma unroll
    for (int o = 16; o; o >>= 1) m = fmaxf(m, __shfl_xor_sync(0xffffffffu, m, o));
    float s2 = __expf(v0 - m) + ((lane < 8) ? __expf(v1 - m) : 0.f);
#pragma unroll
    for (int o = 16; o; o >>= 1) s2 += __shfl_xor_sync(0xffffffffu, s2, o);
    float lse = m + __logf(s2);
    out[gw * C2 + lane] = v0 - lse;
    if (lane < 8) out[gw * C2 + 32 + lane] = v1 - lse;
}

// ================= launch =================
extern "C" void kernel_launch(void* const* d_in, const int* in_sizes, int n_in,
                              void* d_out, int out_size) {
    const float* x   = (const float*)d_in[0];
    const int*   ei  = (const int*)  d_in[1];
    const float* W1  = (const float*)d_in[2];
    const float* as1 = (const float*)d_in[3];
    const float* ad1 = (const float*)d_in[4];
    const float* b1  = (const float*)d_in[5];
    const float* W2  = (const float*)d_in[6];
    const float* as2 = (const float*)d_in[7];
    const float* ad2 = (const float*)d_in[8];
    const float* b2  = (const float*)d_in[9];
    float* out = (float*)d_out;

    const int EB = (ET + 255) / 256;

    zero_prep_kernel<<<(NN + 255) / 256, 256>>>(W2, as2, ad2);
    hist_kernel     <<<EB, 256>>>(ei);
    scan_a_kernel   <<<NCHUNK, 256>>>();
    gemm1_kernel    <<<(NN + 63) / 64, 128>>>(x, W1, as1, ad1);  // 4th launch -> profiled
    scan_b_kernel   <<<1, 128>>>();
    scan_c_kernel   <<<NCHUNK, 256>>>();
    scatter_kernel  <<<EB, 256>>>(ei);
    gather1_kernel  <<<(NN * 32 + 255) / 256, 256>>>(b1);
    gemm2_kernel    <<<(NN + 127) / 128, 256>>>(W2);
    gather2_kernel  <<<(NN * 32 + 255) / 256, 256>>>(b2, out);
}

// round 17
// speedup vs baseline: 1.3798x; 1.0245x over previous
#include <cuda_runtime.h>
#include <cuda_fp16.h>
#include <mma.h>
using namespace nvcuda;

#define NN   100000
#define EE   1600000
#define ET   (EE + NN)        // 1,700,000 incl self-loops
#define FIN  128
#define H1   8
#define C1   64
#define C2   40
#define NEG  0.2f
#define NCHUNK 98             // ceil(NN/1024)

// ---------------- scratch (device globals; allocation-free) ----------------
__device__ int     g_cnt [NN];
__device__ int     g_row [NN + 1];
__device__ int     g_cur [NN];
__device__ int     g_srcs[ET];
__device__ int     g_csum[NCHUNK];
__device__ int     g_coff[NCHUNK];
__device__ __half2 g_h1h [NN * 32];   // h1 fp16, 32 half2 per node
__device__ float   g_as1 [NN * H1];
__device__ float   g_ad1 [NN * H1];
__device__ float   g_x2  [NN * C1];   // layer-2 input (post attention+lrelu)
__device__ float   g_h2  [NN * C2];
__device__ float   g_as2 [NN];
__device__ float   g_ad2 [NN];
__device__ float   g_va  [C1];
__device__ float   g_vd  [C1];

__device__ __forceinline__ float lrelu(float x) { return x > 0.f ? x : NEG * x; }

// ---- stream/event resources, created once at program init (no device memory) ----
struct KLResources {
    cudaStream_t side;
    cudaEvent_t  ev_fork, ev_join;
    KLResources() {
        cudaStreamCreateWithFlags(&side, cudaStreamNonBlocking);
        cudaEventCreateWithFlags(&ev_fork, cudaEventDisableTiming);
        cudaEventCreateWithFlags(&ev_join, cudaEventDisableTiming);
    }
};
static KLResources g_kl;

// ================= zero counters + va/vd precompute =================
__global__ __launch_bounds__(256) void zero_prep_kernel(const float* __restrict__ W2,
                                                        const float* __restrict__ asw,
                                                        const float* __restrict__ adw) {
    int i = blockIdx.x * 256 + threadIdx.x;
    if (i < NN) g_cnt[i] = 0;
    if (i < C1) {
        float s = 0.f, d = 0.f;
#pragma unroll
        for (int j = 0; j < C2; j++) { float w = W2[i * C2 + j]; s += w * asw[j]; d += w * adw[j]; }
        g_va[i] = s;
        g_vd[i] = d;
    }
}

// ================= CSR build =================
__global__ __launch_bounds__(256) void hist_kernel(const int* __restrict__ ei) {
    int e = blockIdx.x * 256 + threadIdx.x;
    if (e >= ET) return;
    int dst = (e < EE) ? ei[EE + e] : (e - EE);
    atomicAdd(&g_cnt[dst], 1);
}

__global__ __launch_bounds__(256) void scan_a_kernel() {
    __shared__ int sred[256];
    const int c = blockIdx.x, tid = threadIdx.x;
    int base = c * 1024 + tid * 4, s = 0;
#pragma unroll
    for (int i = 0; i < 4; i++) { int idx = base + i; if (idx < NN) s += g_cnt[idx]; }
    sred[tid] = s;
    __syncthreads();
    for (int o = 128; o; o >>= 1) {
        if (tid < o) sred[tid] += sred[tid + o];
        __syncthreads();
    }
    if (tid == 0) g_csum[c] = sred[0];
}

__global__ __launch_bounds__(128) void scan_b_kernel() {
    __shared__ int ws[4], wofs[4];
    const int t = threadIdx.x, lane = t & 31, warp = t >> 5;
    int v = (t < NCHUNK) ? g_csum[t] : 0;
    int incl = v;
#pragma unroll
    for (int o = 1; o < 32; o <<= 1) {
        int n = __shfl_up_sync(0xffffffffu, incl, o);
        if (lane >= o) incl += n;
    }
    if (lane == 31) ws[warp] = incl;
    __syncthreads();
    if (t == 0) { int a = 0; for (int w = 0; w < 4; w++) { wofs[w] = a; a += ws[w]; } }
    __syncthreads();
    if (t < NCHUNK) g_coff[t] = incl - v + wofs[warp];
}

__global__ __launch_bounds__(256) void scan_c_kernel() {
    __shared__ int ws[8], wofs[8];
    const int c = blockIdx.x, tid = threadIdx.x, lane = tid & 31, warp = tid >> 5;
    int base = c * 1024 + tid * 4;
    int v[4], s = 0;
#pragma unroll
    for (int i = 0; i < 4; i++) {
        int idx = base + i;
        v[i] = (idx < NN) ? g_cnt[idx] : 0;
        s += v[i];
    }
    int incl = s;
#pragma unroll
    for (int o = 1; o < 32; o <<= 1) {
        int n = __shfl_up_sync(0xffffffffu, incl, o);
        if (lane >= o) incl += n;
    }
    if (lane == 31) ws[warp] = incl;
    __syncthreads();
    if (tid == 0) { int a = 0; for (int w = 0; w < 8; w++) { wofs[w] = a; a += ws[w]; } }
    __syncthreads();
    int p = incl - s + wofs[warp] + g_coff[c];
#pragma unroll
    for (int i = 0; i < 4; i++) {
        int idx = base + i;
        if (idx < NN) {
            g_row[idx] = p;
            g_cur[idx] = p;
            p += v[i];
            if (idx == NN - 1) g_row[NN] = p;
        }
    }
}

__global__ __launch_bounds__(256) void scatter_kernel(const int* __restrict__ ei) {
    int e = blockIdx.x * 256 + threadIdx.x;
    if (e >= ET) return;
    int src, dst;
    if (e < EE) { src = ei[e]; dst = ei[EE + e]; }
    else        { src = dst = e - EE; }
    int pos = atomicAdd(&g_cur[dst], 1);
    g_srcs[pos] = src;
}

// ================= layer1 GEMM via fp16 wmma, occupancy-first (R13-validated) ==========
// 128 threads (4 warps), 64 nodes/block. x-tile + FULL W1 staged once; no
// mid-loop syncs. warp w computes rows [16w,16w+16) x all 64 channels, K=128.
#define XH_LD 136        // 64 rows x 136 half (pad 8)  = 17,408 B
#define WH_LD 72         // 128 rows x 72 half (pad 8)  = 18,432 B
#define CB_LD 68         // 64 rows x 68 f32 (epilogue) = 17,408 B (aliases xh)
__global__ __launch_bounds__(128, 6) void gemm1_kernel(const float* __restrict__ x,
                                                       const float* __restrict__ W1,
                                                       const float* __restrict__ asw,
                                                       const float* __restrict__ adw) {
    __shared__ __align__(16) unsigned char sraw[64 * XH_LD * 2 + 128 * WH_LD * 2]; // 35,840 B
    __half* xh = (__half*)sraw;                          // [64][136]
    __half* wh = (__half*)(sraw + 64 * XH_LD * 2);       // [128][72]
    float*  cb = (float*)sraw;                           // [64][68] (aliases xh post-mainloop)

    const int tid = threadIdx.x, warp = tid >> 5;
    const int node0 = blockIdx.x * 64;
    const float4* x4 = (const float4*)x;
    const float4* W4 = (const float4*)W1;

    // stage x tile: 64 rows x 32 float4 = 2048 over 128 threads
#pragma unroll
    for (int i = 0; i < 16; i++) {
        int idx = tid + i * 128;
        int node = idx >> 5, kq = idx & 31;
        int gn = node0 + node; if (gn >= NN) gn = NN - 1;
        float4 v = x4[(size_t)gn * 32 + kq];
        __half2* dp = (__half2*)&xh[node * XH_LD + kq * 4];
        dp[0] = __floats2half2_rn(v.x, v.y);
        dp[1] = __floats2half2_rn(v.z, v.w);
    }
    // stage full W1: 128 rows x 16 float4 = 2048 over 128 threads
#pragma unroll
    for (int i = 0; i < 16; i++) {
        int idx = tid + i * 128;
        int k = idx >> 4, cq = idx & 15;
        float4 w = W4[(size_t)k * 16 + cq];
        __half2* dp = (__half2*)&wh[k * WH_LD + cq * 4];
        dp[0] = __floats2half2_rn(w.x, w.y);
        dp[1] = __floats2half2_rn(w.z, w.w);
    }
    __syncthreads();

    wmma::fragment<wmma::accumulator, 16, 16, 16, float> c[4];
#pragma unroll
    for (int n = 0; n < 4; n++) wmma::fill_fragment(c[n], 0.f);

#pragma unroll
    for (int ks = 0; ks < 8; ks++) {
        wmma::fragment<wmma::matrix_a, 16, 16, 16, __half, wmma::row_major> a;
        wmma::load_matrix_sync(a, xh + (warp * 16) * XH_LD + ks * 16, XH_LD);
#pragma unroll
        for (int n = 0; n < 4; n++) {
            wmma::fragment<wmma::matrix_b, 16, 16, 16, __half, wmma::row_major> b;
            wmma::load_matrix_sync(b, wh + (ks * 16) * WH_LD + n * 16, WH_LD);
            wmma::mma_sync(c[n], a, b, c[n]);
        }
    }
    __syncthreads();            // xh dead -> reuse as cb
#pragma unroll
    for (int n = 0; n < 4; n++)
        wmma::store_matrix_sync(cb + (warp * 16) * CB_LD + n * 16, c[n], CB_LD, wmma::mem_row_major);
    __syncthreads();

    // epilogue: 2 threads/node; h selects channels [32h, 32h+32) = heads 4h..4h+3
    const int node = tid >> 1, h = tid & 1;
    const int gn = node0 + node;
    const float* row = cb + node * CB_LD + h * 32;
    if (gn < NN) {
#pragma unroll
        for (int hh = 0; hh < 4; hh++) {
            int head = h * 4 + hh;
            float ps = 0.f, pd = 0.f;
#pragma unroll
            for (int j = 0; j < 8; j++) {
                float cv = row[hh * 8 + j];
                ps += cv * asw[head * 8 + j];
                pd += cv * adw[head * 8 + j];
            }
            g_as1[gn * H1 + head] = ps;
            g_ad1[gn * H1 + head] = pd;
        }
#pragma unroll
        for (int q = 0; q < 16; q++)
            g_h1h[gn * 32 + h * 16 + q] = __floats2half2_rn(row[2 * q], row[2 * q + 1]);
    }
}

// ====== layer1 gather (fp16 h1) + fused layer2-input transform (R13-validated) ======
// warp per dst node; lane handles channel pair (2*lane, 2*lane+1), head = lane>>2
__global__ __launch_bounds__(256) void gather1_kernel(const float* __restrict__ b1) {
    const int gw = (blockIdx.x * 256 + threadIdx.x) >> 5;
    const int lane = threadIdx.x & 31;
    if (gw >= NN) return;
    const int beg = g_row[gw], end = g_row[gw + 1];

    const float myad = (lane < H1) ? g_ad1[gw * H1 + lane] : 0.f;
    float accx = 0.f, accy = 0.f, den = 0.f;

    for (int base = beg; base < end; base += 32) {
        int nv = end - base; if (nv > 32) nv = 32;
        int s = g_srcs[base + (lane < nv ? lane : 0)];
        for (int j = 0; j < nv; j++) {
            int src = __shfl_sync(0xffffffffu, s, j);
            float myw = 0.f;
            if (lane < H1)
                myw = __expf(lrelu(g_as1[src * H1 + lane] + myad));
            den += myw;                                        // lanes 0-7: per-head den
            float w = __shfl_sync(0xffffffffu, myw, lane >> 2);
            float2 f = __half22float2(g_h1h[src * 32 + lane]);
            accx += f.x * w;
            accy += f.y * w;
        }
    }
    // fused: x2 = lrelu(agg/den + b1)
    float d = __shfl_sync(0xffffffffu, den, lane >> 2);
    float2 bb = *(const float2*)&b1[2 * lane];
    float2 o;
    o.x = lrelu(__fdividef(accx, d) + bb.x);
    o.y = lrelu(__fdividef(accy, d) + bb.y);
    *(float2*)&g_x2[gw * C1 + 2 * lane] = o;
}

// ================= layer2 GEMM: h2 = x2@W2; logits via va/vd (R13-validated) ==========
// 256 threads, 128 nodes/block, 4 nodes/thread
__global__ __launch_bounds__(256) void gemm2_kernel(const float* __restrict__ W2) {
    __shared__ float sW2[C1 * C2];       // 10KB
    __shared__ float sx2[128 * 65];      // 33.3KB (stride 65 -> conflict-free col reads)
    __shared__ float sva[C1], svd[C1];
    const int tid = threadIdx.x;
    const int node0 = blockIdx.x * 128;

    for (int i = tid; i < C1 * C2; i += 256) sW2[i] = W2[i];
    if (tid < C1) { sva[tid] = g_va[tid]; svd[tid] = g_vd[tid]; }
    for (int i = tid; i < 128 * C1 / 4; i += 256) {
        int node = i >> 4, cq = i & 15;
        int gn = node0 + node;
        float4 v = make_float4(0.f, 0.f, 0.f, 0.f);
        if (gn < NN) v = *(const float4*)&g_x2[gn * C1 + cq * 4];
        float* dstp = &sx2[node * 65 + cq * 4];   // scalar stores (row stride not 16B aligned)
        dstp[0] = v.x; dstp[1] = v.y; dstp[2] = v.z; dstp[3] = v.w;
    }
    __syncthreads();

    const int lane = tid & 31, grp = tid >> 5, ob = grp * 5;
    float acc[4][5] = {};
#pragma unroll 4
    for (int k = 0; k < C1; k++) {
        float w0 = sW2[k * C2 + ob + 0], w1 = sW2[k * C2 + ob + 1],
              w2 = sW2[k * C2 + ob + 2], w3 = sW2[k * C2 + ob + 3],
              w4 = sW2[k * C2 + ob + 4];
#pragma unroll
        for (int i = 0; i < 4; i++) {
            float xv = sx2[(lane + 32 * i) * 65 + k];
            acc[i][0] += xv * w0; acc[i][1] += xv * w1; acc[i][2] += xv * w2;
            acc[i][3] += xv * w3; acc[i][4] += xv * w4;
        }
    }
#pragma unroll
    for (int i = 0; i < 4; i++) {
        int gn = node0 + lane + 32 * i;
        if (gn < NN) {
#pragma unroll
            for (int j = 0; j < 5; j++) g_h2[gn * C2 + ob + j] = acc[i][j];
        }
    }

    // logits: 2 threads per node, 32 channels each
    const int node = tid >> 1, h = tid & 1;
    const int gn = node0 + node;
    float s = 0.f, d = 0.f;
    const float* xr = &sx2[node * 65 + h * 32];
    const float* va = &sva[h * 32];
    const float* vd = &svd[h * 32];
#pragma unroll 8
    for (int k = 0; k < 32; k++) { float xv = xr[k]; s += xv * va[k]; d += xv * vd[k]; }
    s += __shfl_xor_sync(0xffffffffu, s, 1);
    d += __shfl_xor_sync(0xffffffffu, d, 1);
    if (h == 0 && gn < NN) { g_as2[gn] = s; g_ad2[gn] = d; }
}

// ====== layer2 gather + FUSED log_softmax: warp per dst node, atomic-free ======
__global__ __launch_bounds__(256) void gather2_kernel(const float* __restrict__ b2,
                                                      float* __restrict__ out) {
    const int gw = (blockIdx.x * 256 + threadIdx.x) >> 5;
    const int lane = threadIdx.x & 31;
    if (gw >= NN) return;
    const int beg = g_row[gw], end = g_row[gw + 1];

    const float myad = g_ad2[gw];
    float acc0 = 0.f, acc1 = 0.f, den = 0.f;

    for (int base = beg; base < end; base += 32) {
        int nv = end - base; if (nv > 32) nv = 32;
        int s = g_srcs[base + (lane < nv ? lane : 0)];
        float wl = __expf(lrelu(g_as2[s] + myad));   // per-lane precomputed weight
        for (int j = 0; j < nv; j++) {
            int src = __shfl_sync(0xffffffffu, s, j);
            float w = __shfl_sync(0xffffffffu, wl, j);
            acc0 += g_h2[src * C2 + lane] * w;
            if (lane < 8) acc1 += g_h2[src * C2 + 32 + lane] * w;
            den += w;                                // identical across lanes
        }
    }

    // fused log_softmax over the 40 in-register channels
    const float inv = __fdividef(1.f, den);
    float v0 = acc0 * inv + b2[lane];
    float v1 = (lane < 8) ? acc1 * inv + b2[32 + lane] : -1e30f;
    float m = fmaxf(v0, v1);
#pragma unroll
    for (int o = 16; o; o >>= 1) m = fmaxf(m, __shfl_xor_sync(0xffffffffu, m, o));
    float s2 = __expf(v0 - m) + ((lane < 8) ? __expf(v1 - m) : 0.f);
#pragma unroll
    for (int o = 16; o; o >>= 1) s2 += __shfl_xor_sync(0xffffffffu, s2, o);
    float lse = m + __logf(s2);
    out[gw * C2 + lane] = v0 - lse;
    if (lane < 8) out[gw * C2 + 32 + lane] = v1 - lse;
}

// ================= launch: fork CSR build onto side stream, overlap with gemm1 =========
extern "C" void kernel_launch(void* const* d_in, const int* in_sizes, int n_in,
                              void* d_out, int out_size) {
    const float* x   = (const float*)d_in[0];
    const int*   ei  = (const int*)  d_in[1];
    const float* W1  = (const float*)d_in[2];
    const float* as1 = (const float*)d_in[3];
    const float* ad1 = (const float*)d_in[4];
    const float* b1  = (const float*)d_in[5];
    const float* W2  = (const float*)d_in[6];
    const float* as2 = (const float*)d_in[7];
    const float* ad2 = (const float*)d_in[8];
    const float* b2  = (const float*)d_in[9];
    float* out = (float*)d_out;

    const int EB = (ET + 255) / 256;
    cudaStream_t side = g_kl.side;

    // main stream: zero counters + va/vd (needed by both branches)
    zero_prep_kernel<<<(NN + 255) / 256, 256>>>(W2, as2, ad2);

    // fork: CSR build on side stream
    cudaEventRecord(g_kl.ev_fork, 0);
    cudaStreamWaitEvent(side, g_kl.ev_fork, 0);
    hist_kernel    <<<EB, 256, 0, side>>>(ei);
    scan_a_kernel  <<<NCHUNK, 256, 0, side>>>();
    scan_b_kernel  <<<1, 128, 0, side>>>();
    scan_c_kernel  <<<NCHUNK, 256, 0, side>>>();
    scatter_kernel <<<EB, 256, 0, side>>>(ei);
    cudaEventRecord(g_kl.ev_join, side);

    // main stream: gemm1 overlaps the CSR build
    gemm1_kernel   <<<(NN + 63) / 64, 128>>>(x, W1, as1, ad1);

    // join: gather1 needs CSR + gemm1
    cudaStreamWaitEvent(0, g_kl.ev_join, 0);
    gather1_kernel <<<(NN * 32 + 255) / 256, 256>>>(b1);
    gemm2_kernel   <<<(NN + 127) / 128, 256>>>(W2);
    gather2_kernel <<<(NN * 32 + 255) / 256, 256>>>(b2, out);
}